// round 3
// baseline (speedup 1.0000x reference)
#include <cuda_runtime.h>
#include <cuda_bf16.h>
#include <cstdint>

#define B_ 2
#define S_ 2048
#define E_ 1024
#define H_ 16
#define D_ 64
#define M_ (B_*S_)   // 4096 rows

// ---------------- scratch (device globals; no allocation) -------------------
__device__ float g_Q[M_*E_];
__device__ float g_K[M_*E_];
__device__ float g_V[M_*E_];
__device__ float g_A[M_*E_];
__device__ __align__(16) __nv_bfloat16 g_act_hi[M_*E_];
__device__ __align__(16) __nv_bfloat16 g_act_lo[M_*E_];
__device__ __align__(16) __nv_bfloat16 g_w_hi[E_*E_];
__device__ __align__(16) __nv_bfloat16 g_w_lo[E_*E_];

// ---------------- PTX helpers ----------------------------------------------
__device__ __forceinline__ uint32_t smem_u32(const void* p) {
    uint32_t a;
    asm("{ .reg .u64 t; cvta.to.shared.u64 t, %1; cvt.u32.u64 %0, t; }"
        : "=r"(a) : "l"(p));
    return a;
}
__device__ __forceinline__ void cp16(uint32_t dst, const void* src) {
    asm volatile("cp.async.cg.shared.global [%0], [%1], 16;" :: "r"(dst), "l"(src));
}
#define CP_COMMIT() asm volatile("cp.async.commit_group;" ::: "memory")

__device__ __forceinline__ void ldsm_x4(uint32_t& r0, uint32_t& r1,
                                        uint32_t& r2, uint32_t& r3, uint32_t addr) {
    asm volatile("ldmatrix.sync.aligned.m8n8.x4.shared.b16 {%0,%1,%2,%3}, [%4];"
                 : "=r"(r0), "=r"(r1), "=r"(r2), "=r"(r3) : "r"(addr));
}
__device__ __forceinline__ void mma_bf16(float* d, const uint32_t* a,
                                         uint32_t b0, uint32_t b1) {
    asm volatile(
        "mma.sync.aligned.m16n8k16.row.col.f32.bf16.bf16.f32 "
        "{%0,%1,%2,%3}, {%4,%5,%6,%7}, {%8,%9}, {%0,%1,%2,%3};"
        : "+f"(d[0]), "+f"(d[1]), "+f"(d[2]), "+f"(d[3])
        : "r"(a[0]), "r"(a[1]), "r"(a[2]), "r"(a[3]), "r"(b0), "r"(b1));
}
__device__ __forceinline__ uint32_t sw128(uint32_t off) {
    return off ^ ((off >> 3) & 0x70);
}

// ---------------------------------------------------------------------------
// Split fp32 -> (hi, lo) bf16 pair. n4 = n/4.
// ---------------------------------------------------------------------------
__global__ __launch_bounds__(256)
void split_bf16(const float* __restrict__ x, __nv_bfloat16* __restrict__ hi,
                __nv_bfloat16* __restrict__ lo, int n4)
{
    int i = blockIdx.x * blockDim.x + threadIdx.x;
    if (i >= n4) return;
    float4 v = ((const float4*)x)[i];
    __nv_bfloat16 h0 = __float2bfloat16(v.x);
    __nv_bfloat16 h1 = __float2bfloat16(v.y);
    __nv_bfloat16 h2 = __float2bfloat16(v.z);
    __nv_bfloat16 h3 = __float2bfloat16(v.w);
    __nv_bfloat16 l0 = __float2bfloat16(v.x - __bfloat162float(h0));
    __nv_bfloat16 l1 = __float2bfloat16(v.y - __bfloat162float(h1));
    __nv_bfloat16 l2 = __float2bfloat16(v.z - __bfloat162float(h2));
    __nv_bfloat16 l3 = __float2bfloat16(v.w - __bfloat162float(h3));
    __nv_bfloat162 ph0; ph0.x = h0; ph0.y = h1;
    __nv_bfloat162 ph1; ph1.x = h2; ph1.y = h3;
    __nv_bfloat162 pl0; pl0.x = l0; pl0.y = l1;
    __nv_bfloat162 pl1; pl1.x = l2; pl1.y = l3;
    ((__nv_bfloat162*)hi)[i*2]   = ph0;
    ((__nv_bfloat162*)hi)[i*2+1] = ph1;
    ((__nv_bfloat162*)lo)[i*2]   = pl0;
    ((__nv_bfloat162*)lo)[i*2+1] = pl1;
}

// ---------------------------------------------------------------------------
// HMMA GEMM: C[m][n] = sum over 3 slabs of Aslab[m][k]*Bslab[n][k]  (fp32 out)
// slabs: (Ahi,Bhi), (Alo,Bhi), (Ahi,Blo).
// CTA tile 128x128, BK=64 bf16. 8 warps, warp tile 64x32 (4x4 m16n8k16 frags).
// Double-buffered cp.async; SW128-swizzled smem; ldmatrix.x4 fragment loads.
// ---------------------------------------------------------------------------
#define GEMM_BK 64
#define GEMM_NIT 48                   // 3 slabs * (1024/64)
#define ATILE_B (128*128)             // 128 rows x 64 bf16 = 128B/row -> 16KB
#define STAGE_B (2*ATILE_B)           // A + B per stage = 32KB
#define GEMM_SMEM (2*STAGE_B)         // 64KB

__device__ __forceinline__ void gemm_load_tiles(
    const __nv_bfloat16* __restrict__ Ap, const __nv_bfloat16* __restrict__ Bp,
    int m0, int n0, int kc, uint32_t sa, uint32_t sbb, int tid)
{
#pragma unroll
    for (int i = 0; i < 4; i++) {
        int cidx = tid + i*256;          // 0..1023
        int row = cidx >> 3;             // 0..127
        int cb  = (cidx & 7) * 16;       // byte col within 128B row
        uint32_t sw = sw128((uint32_t)(row*128 + cb));
        cp16(sa  + sw, (const char*)(Ap + (size_t)(m0+row)*E_ + kc) + cb);
        cp16(sbb + sw, (const char*)(Bp + (size_t)(n0+row)*E_ + kc) + cb);
    }
}

__global__ __launch_bounds__(256)
void gemm_hmma(const __nv_bfloat16* __restrict__ Ahi, const __nv_bfloat16* __restrict__ Alo,
               const __nv_bfloat16* __restrict__ Bhi, const __nv_bfloat16* __restrict__ Blo,
               float* __restrict__ C)
{
    extern __shared__ char smem[];
    const uint32_t sb = smem_u32(smem);
    const int tid  = threadIdx.x;
    const int lane = tid & 31;
    const int wid  = tid >> 5;
    const int m0 = blockIdx.y * 128;
    const int n0 = blockIdx.x * 128;
    const int wm = (wid & 1) * 64;      // warp m offset in tile
    const int wn = (wid >> 1) * 32;     // warp n offset in tile

    float acc[4][4][4];
#pragma unroll
    for (int mi = 0; mi < 4; mi++)
#pragma unroll
        for (int ni = 0; ni < 4; ni++)
#pragma unroll
            for (int q = 0; q < 4; q++) acc[mi][ni][q] = 0.f;

    // per-lane ldmatrix address components (byte offsets before swizzle)
    const int lrow = lane & 15;          // row within 16-row frag
    const int lcb  = (lane >> 4) * 16;   // 0 or 16 bytes (k half)

    // prologue: stage 0 <- iter 0 (slab 0, kc 0)
    gemm_load_tiles(Ahi, Bhi, m0, n0, 0, sb, sb + ATILE_B, tid);
    CP_COMMIT();

    for (int iter = 0; iter < GEMM_NIT; iter++) {
        const int s = iter & 1;
        if (iter + 1 < GEMM_NIT) {
            const int nit  = iter + 1;
            const int slab = nit >> 4;
            const int kc   = (nit & 15) * GEMM_BK;
            const __nv_bfloat16* Ap = (slab == 1) ? Alo : Ahi;
            const __nv_bfloat16* Bp = (slab == 2) ? Blo : Bhi;
            gemm_load_tiles(Ap, Bp, m0, n0, kc,
                            sb + (s^1)*STAGE_B, sb + (s^1)*STAGE_B + ATILE_B, tid);
            CP_COMMIT();
            asm volatile("cp.async.wait_group 1;" ::: "memory");
        } else {
            asm volatile("cp.async.wait_group 0;" ::: "memory");
        }
        __syncthreads();

        const uint32_t sa  = sb + s*STAGE_B;
        const uint32_t sbb = sa + ATILE_B;

#pragma unroll
        for (int kk = 0; kk < 4; kk++) {
            uint32_t a[4][4], bfr[2][4];
#pragma unroll
            for (int mi = 0; mi < 4; mi++) {
                uint32_t off = (uint32_t)((wm + mi*16 + lrow)*128 + kk*32 + lcb);
                ldsm_x4(a[mi][0], a[mi][1], a[mi][2], a[mi][3], sa + sw128(off));
            }
#pragma unroll
            for (int h = 0; h < 2; h++) {
                uint32_t off = (uint32_t)((wn + h*16 + lrow)*128 + kk*32 + lcb);
                ldsm_x4(bfr[h][0], bfr[h][1], bfr[h][2], bfr[h][3], sbb + sw128(off));
            }
#pragma unroll
            for (int mi = 0; mi < 4; mi++) {
                mma_bf16(acc[mi][0], a[mi], bfr[0][0], bfr[0][2]);
                mma_bf16(acc[mi][1], a[mi], bfr[0][1], bfr[0][3]);
                mma_bf16(acc[mi][2], a[mi], bfr[1][0], bfr[1][2]);
                mma_bf16(acc[mi][3], a[mi], bfr[1][1], bfr[1][3]);
            }
        }
        __syncthreads();
    }

    // epilogue: D frag (m16n8): d0,d1 @ (r, c), d2,d3 @ (r+8, c); c = 2*(lane%4)
    const int r  = lane >> 2;
    const int c2 = (lane & 3) * 2;
#pragma unroll
    for (int mi = 0; mi < 4; mi++) {
#pragma unroll
        for (int ni = 0; ni < 4; ni++) {
            const int row = m0 + wm + mi*16 + r;
            const int col = n0 + wn + ni*8 + c2;
            *(float2*)&C[(size_t)row*E_ + col]     = make_float2(acc[mi][ni][0], acc[mi][ni][1]);
            *(float2*)&C[(size_t)(row+8)*E_ + col] = make_float2(acc[mi][ni][2], acc[mi][ni][3]);
        }
    }
}

// ---------------------------------------------------------------------------
// Flash attention (fp32, causal) — unchanged from R1.
// ---------------------------------------------------------------------------
#define FA_STRIDE 68
#define FA_SMEM (3 * 64 * FA_STRIDE * 4)

__global__ __launch_bounds__(256)
void flash_attn(const float* __restrict__ Q, const float* __restrict__ K,
                const float* __restrict__ V, float* __restrict__ O)
{
    extern __shared__ float sm[];
    float* Qs = sm;
    float* Ks = sm + 64 * FA_STRIDE;
    float* Vs = sm + 2 * 64 * FA_STRIDE;

    const int tid = threadIdx.x;
    const int tx = tid & 15;
    const int ty = tid >> 4;
    const int tm = ty * 4;
    const int tn = tx * 4;

    const int q0 = blockIdx.x * 64;
    const int h  = blockIdx.y;
    const int b  = blockIdx.z;

    const size_t base = (size_t)(b * S_) * E_ + h * 64;

#pragma unroll
    for (int c = 0; c < 4; c++) {
        int f4 = tid + c * 256;
        int r  = f4 >> 4;
        int d4 = (f4 & 15) * 4;
        float4 v = *(const float4*)&Q[base + (size_t)(q0 + r) * E_ + d4];
        Qs[(d4 + 0) * FA_STRIDE + r] = v.x;
        Qs[(d4 + 1) * FA_STRIDE + r] = v.y;
        Qs[(d4 + 2) * FA_STRIDE + r] = v.z;
        Qs[(d4 + 3) * FA_STRIDE + r] = v.w;
    }

    float o[4][4];
    float m_i[4], l_i[4];
#pragma unroll
    for (int i = 0; i < 4; i++) {
        m_i[i] = -1e30f; l_i[i] = 0.f;
#pragma unroll
        for (int j = 0; j < 4; j++) o[i][j] = 0.f;
    }

    for (int k0 = 0; k0 <= q0; k0 += 64) {
        __syncthreads();
#pragma unroll
        for (int c = 0; c < 4; c++) {
            int f4 = tid + c * 256;
            int r  = f4 >> 4;
            int d4 = (f4 & 15) * 4;
            float4 kv = *(const float4*)&K[base + (size_t)(k0 + r) * E_ + d4];
            Ks[(d4 + 0) * FA_STRIDE + r] = kv.x;
            Ks[(d4 + 1) * FA_STRIDE + r] = kv.y;
            Ks[(d4 + 2) * FA_STRIDE + r] = kv.z;
            Ks[(d4 + 3) * FA_STRIDE + r] = kv.w;
            float4 vv = *(const float4*)&V[base + (size_t)(k0 + r) * E_ + d4];
            *(float4*)&Vs[r * FA_STRIDE + d4] = vv;
        }
        __syncthreads();

        float s[4][4];
#pragma unroll
        for (int i = 0; i < 4; i++)
#pragma unroll
            for (int j = 0; j < 4; j++) s[i][j] = 0.f;

#pragma unroll 8
        for (int d = 0; d < 64; d++) {
            float4 qv = *(const float4*)&Qs[d * FA_STRIDE + tm];
            float4 kv = *(const float4*)&Ks[d * FA_STRIDE + tn];
            float qa[4] = {qv.x, qv.y, qv.z, qv.w};
            float kb[4] = {kv.x, kv.y, kv.z, kv.w};
#pragma unroll
            for (int i = 0; i < 4; i++)
#pragma unroll
                for (int j = 0; j < 4; j++)
                    s[i][j] = fmaf(qa[i], kb[j], s[i][j]);
        }
#pragma unroll
        for (int i = 0; i < 4; i++)
#pragma unroll
            for (int j = 0; j < 4; j++) s[i][j] *= 0.125f;

        if (k0 == q0) {
#pragma unroll
            for (int i = 0; i < 4; i++)
#pragma unroll
                for (int j = 0; j < 4; j++)
                    if (tn + j > tm + i) s[i][j] = -1e9f;
        }

        float mnew[4], scal[4];
#pragma unroll
        for (int i = 0; i < 4; i++) {
            float rm = fmaxf(fmaxf(s[i][0], s[i][1]), fmaxf(s[i][2], s[i][3]));
#pragma unroll
            for (int off = 8; off >= 1; off >>= 1)
                rm = fmaxf(rm, __shfl_xor_sync(0xffffffffu, rm, off));
            mnew[i] = fmaxf(m_i[i], rm);
            scal[i] = __expf(m_i[i] - mnew[i]);
            float sum = 0.f;
#pragma unroll
            for (int j = 0; j < 4; j++) {
                s[i][j] = __expf(s[i][j] - mnew[i]);
                sum += s[i][j];
            }
#pragma unroll
            for (int off = 8; off >= 1; off >>= 1)
                sum += __shfl_xor_sync(0xffffffffu, sum, off);
            l_i[i] = l_i[i] * scal[i] + sum;
            m_i[i] = mnew[i];
#pragma unroll
            for (int j = 0; j < 4; j++) o[i][j] *= scal[i];
        }

        __syncthreads();
        float* Ps = Ks;
#pragma unroll
        for (int j = 0; j < 4; j++)
            *(float4*)&Ps[(tn + j) * FA_STRIDE + tm] =
                make_float4(s[0][j], s[1][j], s[2][j], s[3][j]);
        __syncthreads();

#pragma unroll 8
        for (int kk = 0; kk < 64; kk++) {
            float4 pv = *(const float4*)&Ps[kk * FA_STRIDE + tm];
            float4 vv = *(const float4*)&Vs[kk * FA_STRIDE + tn];
            float pa[4] = {pv.x, pv.y, pv.z, pv.w};
            float vb[4] = {vv.x, vv.y, vv.z, vv.w};
#pragma unroll
            for (int i = 0; i < 4; i++)
#pragma unroll
                for (int j = 0; j < 4; j++)
                    o[i][j] = fmaf(pa[i], vb[j], o[i][j]);
        }
    }

#pragma unroll
    for (int i = 0; i < 4; i++) {
        float inv = 1.f / l_i[i];
        float* op = &O[base + (size_t)(q0 + tm + i) * E_ + tn];
        *(float4*)op = make_float4(o[i][0] * inv, o[i][1] * inv,
                                   o[i][2] * inv, o[i][3] * inv);
    }
}

// ---------------------------------------------------------------------------
extern "C" void kernel_launch(void* const* d_in, const int* in_sizes, int n_in,
                              void* d_out, int out_size)
{
    const float* query = (const float*)d_in[0];
    const float* key   = (const float*)d_in[1];
    const float* value = (const float*)d_in[2];
    // d_in[3] = mask (causal, structural) — unused
    const float* w_q = (const float*)d_in[4];
    const float* w_k = (const float*)d_in[5];
    const float* w_v = (const float*)d_in[6];
    const float* w_o = (const float*)d_in[7];
    float* out = (float*)d_out;

    float *Qb, *Kb, *Vb, *Ab;
    cudaGetSymbolAddress((void**)&Qb, g_Q);
    cudaGetSymbolAddress((void**)&Kb, g_K);
    cudaGetSymbolAddress((void**)&Vb, g_V);
    cudaGetSymbolAddress((void**)&Ab, g_A);
    __nv_bfloat16 *ah, *al, *wh, *wl;
    cudaGetSymbolAddress((void**)&ah, g_act_hi);
    cudaGetSymbolAddress((void**)&al, g_act_lo);
    cudaGetSymbolAddress((void**)&wh, g_w_hi);
    cudaGetSymbolAddress((void**)&wl, g_w_lo);

    cudaFuncSetAttribute(flash_attn,
                         cudaFuncAttributeMaxDynamicSharedMemorySize, FA_SMEM);
    cudaFuncSetAttribute(gemm_hmma,
                         cudaFuncAttributeMaxDynamicSharedMemorySize, GEMM_SMEM);

    const int actN4 = M_ * E_ / 4;   // 1M
    const int wN4   = E_ * E_ / 4;   // 256K
    dim3 gg(E_ / 128, M_ / 128);     // (8, 32)

    // Q projection
    split_bf16<<<actN4/256, 256>>>(query, ah, al, actN4);
    split_bf16<<<wN4/256,  256>>>(w_q,  wh, wl, wN4);
    gemm_hmma<<<gg, 256, GEMM_SMEM>>>(ah, al, wh, wl, Qb);
    // K projection
    split_bf16<<<actN4/256, 256>>>(key, ah, al, actN4);
    split_bf16<<<wN4/256,  256>>>(w_k, wh, wl, wN4);
    gemm_hmma<<<gg, 256, GEMM_SMEM>>>(ah, al, wh, wl, Kb);
    // V projection
    split_bf16<<<actN4/256, 256>>>(value, ah, al, actN4);
    split_bf16<<<wN4/256,  256>>>(w_v, wh, wl, wN4);
    gemm_hmma<<<gg, 256, GEMM_SMEM>>>(ah, al, wh, wl, Vb);

    flash_attn<<<dim3(S_ / 64, H_, B_), 256, FA_SMEM>>>(Qb, Kb, Vb, Ab);

    // Output projection
    split_bf16<<<actN4/256, 256>>>(Ab, ah, al, actN4);
    split_bf16<<<wN4/256,  256>>>(w_o, wh, wl, wN4);
    gemm_hmma<<<gg, 256, GEMM_SMEM>>>(ah, al, wh, wl, out);
}

// round 4
// speedup vs baseline: 1.0856x; 1.0856x over previous
#include <cuda_runtime.h>
#include <cstdint>

#define B_ 2
#define S_ 2048
#define E_ 1024
#define H_ 16
#define D_ 64
#define M_ (B_*S_)   // 4096 rows

typedef unsigned long long ull;

// Scratch (device globals; no allocation)
__device__ float g_Q[M_*E_];
__device__ float g_K[M_*E_];
__device__ float g_V[M_*E_];
__device__ float g_A[M_*E_];

// ---------------- packed f32x2 helpers --------------------------------------
__device__ __forceinline__ ull pack2(float x, float y) {
    ull r;
    asm("mov.b64 %0, {%1, %2};" : "=l"(r)
        : "r"(__float_as_uint(x)), "r"(__float_as_uint(y)));
    return r;
}
__device__ __forceinline__ ull fma2(ull a, ull b, ull c) {
    ull d;
    asm("fma.rn.f32x2 %0, %1, %2, %3;" : "=l"(d) : "l"(a), "l"(b), "l"(c));
    return d;
}
__device__ __forceinline__ ull mul2(ull a, ull b) {
    ull d;
    asm("mul.rn.f32x2 %0, %1, %2;" : "=l"(d) : "l"(a), "l"(b));
    return d;
}
__device__ __forceinline__ float2 unpack2(ull v) {
    uint32_t lo, hi;
    asm("mov.b64 {%0, %1}, %2;" : "=r"(lo), "=r"(hi) : "l"(v));
    return make_float2(__uint_as_float(lo), __uint_as_float(hi));
}

// ---------------------------------------------------------------------------
// SGEMM "NT" with packed f32x2: C[m][n] = sum_k A[m*K+k] * W[n*K+k]
// Tiles: BM=BN=128, BK=16. 256 threads, 8x8 per-thread micro-tile
// (accumulators held as 8x4 f32x2 pairs along n).
// ---------------------------------------------------------------------------
__global__ __launch_bounds__(256)
void sgemm_nt(const float* __restrict__ A, const float* __restrict__ W,
              float* __restrict__ C, int M, int N, int K)
{
    __shared__ float As[16][132];   // [k][m]
    __shared__ float Bs[16][132];   // [k][n]

    const int tid = threadIdx.x;
    const int m0 = blockIdx.y * 128;
    const int n0 = blockIdx.x * 128;
    const int tx = tid & 15;
    const int ty = tid >> 4;
    const int tm = ty * 8;
    const int tn = tx * 8;

    const int lr = tid >> 2;         // 0..63
    const int lk = (tid & 3) * 4;    // 0,4,8,12

    ull acc[8][4];
#pragma unroll
    for (int i = 0; i < 8; i++)
#pragma unroll
        for (int j = 0; j < 4; j++) acc[i][j] = 0ull;

    for (int k0 = 0; k0 < K; k0 += 16) {
#pragma unroll
        for (int rr = 0; rr < 2; rr++) {
            const int r = lr + rr * 64;
            float4 va = *(const float4*)&A[(size_t)(m0 + r) * K + k0 + lk];
            As[lk + 0][r] = va.x; As[lk + 1][r] = va.y;
            As[lk + 2][r] = va.z; As[lk + 3][r] = va.w;
            float4 vb = *(const float4*)&W[(size_t)(n0 + r) * K + k0 + lk];
            Bs[lk + 0][r] = vb.x; Bs[lk + 1][r] = vb.y;
            Bs[lk + 2][r] = vb.z; Bs[lk + 3][r] = vb.w;
        }
        __syncthreads();

#pragma unroll
        for (int kk = 0; kk < 16; kk++) {
            float a[8];
            float4 t;
            t = *(const float4*)&As[kk][tm];     a[0]=t.x; a[1]=t.y; a[2]=t.z; a[3]=t.w;
            t = *(const float4*)&As[kk][tm + 4]; a[4]=t.x; a[5]=t.y; a[6]=t.z; a[7]=t.w;
            const ull* bp = (const ull*)&Bs[kk][tn];
            ull b0 = bp[0], b1 = bp[1], b2 = bp[2], b3 = bp[3];
#pragma unroll
            for (int i = 0; i < 8; i++) {
                ull ap = pack2(a[i], a[i]);
                acc[i][0] = fma2(ap, b0, acc[i][0]);
                acc[i][1] = fma2(ap, b1, acc[i][1]);
                acc[i][2] = fma2(ap, b2, acc[i][2]);
                acc[i][3] = fma2(ap, b3, acc[i][3]);
            }
        }
        __syncthreads();
    }

#pragma unroll
    for (int i = 0; i < 8; i++) {
        float2 c0 = unpack2(acc[i][0]);
        float2 c1 = unpack2(acc[i][1]);
        float2 c2 = unpack2(acc[i][2]);
        float2 c3 = unpack2(acc[i][3]);
        float* cp = &C[(size_t)(m0 + tm + i) * N + n0 + tn];
        *(float4*)&cp[0] = make_float4(c0.x, c0.y, c1.x, c1.y);
        *(float4*)&cp[4] = make_float4(c2.x, c2.y, c3.x, c3.y);
    }
}

// ---------------------------------------------------------------------------
// Flash attention (fp32 f32x2, causal). One CTA = one (b, h, 64-row q tile).
// 256 threads, 16x16 arrangement, 4x4 micro-tiles (pairs along the col dim).
// ---------------------------------------------------------------------------
#define FA_STRIDE 68
#define FA_SMEM (3 * 64 * FA_STRIDE * 4)

__global__ __launch_bounds__(256)
void flash_attn(const float* __restrict__ Q, const float* __restrict__ K,
                const float* __restrict__ V, float* __restrict__ O)
{
    extern __shared__ float sm[];
    float* Qs = sm;                      // [d][row]
    float* Ks = sm + 64 * FA_STRIDE;     // [d][kk]  (later Ps: [kk][row])
    float* Vs = sm + 2 * 64 * FA_STRIDE; // [kk][d]

    const int tid = threadIdx.x;
    const int tx = tid & 15;
    const int ty = tid >> 4;
    const int tm = ty * 4;
    const int tn = tx * 4;

    const int q0 = blockIdx.x * 64;
    const int h  = blockIdx.y;
    const int b  = blockIdx.z;

    const size_t base = (size_t)(b * S_) * E_ + h * 64;

#pragma unroll
    for (int c = 0; c < 4; c++) {
        int f4 = tid + c * 256;
        int r  = f4 >> 4;
        int d4 = (f4 & 15) * 4;
        float4 v = *(const float4*)&Q[base + (size_t)(q0 + r) * E_ + d4];
        Qs[(d4 + 0) * FA_STRIDE + r] = v.x;
        Qs[(d4 + 1) * FA_STRIDE + r] = v.y;
        Qs[(d4 + 2) * FA_STRIDE + r] = v.z;
        Qs[(d4 + 3) * FA_STRIDE + r] = v.w;
    }

    ull o2[4][2];
    float m_i[4], l_i[4];
#pragma unroll
    for (int i = 0; i < 4; i++) {
        m_i[i] = -1e30f; l_i[i] = 0.f;
        o2[i][0] = 0ull; o2[i][1] = 0ull;
    }

    for (int k0 = 0; k0 <= q0; k0 += 64) {
        __syncthreads();
#pragma unroll
        for (int c = 0; c < 4; c++) {
            int f4 = tid + c * 256;
            int r  = f4 >> 4;
            int d4 = (f4 & 15) * 4;
            float4 kv = *(const float4*)&K[base + (size_t)(k0 + r) * E_ + d4];
            Ks[(d4 + 0) * FA_STRIDE + r] = kv.x;
            Ks[(d4 + 1) * FA_STRIDE + r] = kv.y;
            Ks[(d4 + 2) * FA_STRIDE + r] = kv.z;
            Ks[(d4 + 3) * FA_STRIDE + r] = kv.w;
            float4 vv = *(const float4*)&V[base + (size_t)(k0 + r) * E_ + d4];
            *(float4*)&Vs[r * FA_STRIDE + d4] = vv;
        }
        __syncthreads();

        // S = Q K^T : pairs along the k-column dimension
        ull s2[4][2];
#pragma unroll
        for (int i = 0; i < 4; i++) { s2[i][0] = 0ull; s2[i][1] = 0ull; }

#pragma unroll 8
        for (int d = 0; d < 64; d++) {
            float4 qv = *(const float4*)&Qs[d * FA_STRIDE + tm];
            const ull* kp = (const ull*)&Ks[d * FA_STRIDE + tn];
            ull kb0 = kp[0], kb1 = kp[1];
            ull qp0 = pack2(qv.x, qv.x);
            ull qp1 = pack2(qv.y, qv.y);
            ull qp2 = pack2(qv.z, qv.z);
            ull qp3 = pack2(qv.w, qv.w);
            s2[0][0] = fma2(qp0, kb0, s2[0][0]); s2[0][1] = fma2(qp0, kb1, s2[0][1]);
            s2[1][0] = fma2(qp1, kb0, s2[1][0]); s2[1][1] = fma2(qp1, kb1, s2[1][1]);
            s2[2][0] = fma2(qp2, kb0, s2[2][0]); s2[2][1] = fma2(qp2, kb1, s2[2][1]);
            s2[3][0] = fma2(qp3, kb0, s2[3][0]); s2[3][1] = fma2(qp3, kb1, s2[3][1]);
        }

        float s[4][4];
#pragma unroll
        for (int i = 0; i < 4; i++) {
            float2 lo = unpack2(s2[i][0]);
            float2 hi = unpack2(s2[i][1]);
            s[i][0] = lo.x * 0.125f; s[i][1] = lo.y * 0.125f;
            s[i][2] = hi.x * 0.125f; s[i][3] = hi.y * 0.125f;
        }

        if (k0 == q0) {
#pragma unroll
            for (int i = 0; i < 4; i++)
#pragma unroll
                for (int j = 0; j < 4; j++)
                    if (tn + j > tm + i) s[i][j] = -1e9f;
        }

        // Online softmax update
#pragma unroll
        for (int i = 0; i < 4; i++) {
            float rm = fmaxf(fmaxf(s[i][0], s[i][1]), fmaxf(s[i][2], s[i][3]));
#pragma unroll
            for (int off = 8; off >= 1; off >>= 1)
                rm = fmaxf(rm, __shfl_xor_sync(0xffffffffu, rm, off));
            float mnew = fmaxf(m_i[i], rm);
            float scal = __expf(m_i[i] - mnew);
            float sum = 0.f;
#pragma unroll
            for (int j = 0; j < 4; j++) {
                s[i][j] = __expf(s[i][j] - mnew);
                sum += s[i][j];
            }
#pragma unroll
            for (int off = 8; off >= 1; off >>= 1)
                sum += __shfl_xor_sync(0xffffffffu, sum, off);
            l_i[i] = l_i[i] * scal + sum;
            m_i[i] = mnew;
            ull sp = pack2(scal, scal);
            o2[i][0] = mul2(o2[i][0], sp);
            o2[i][1] = mul2(o2[i][1], sp);
        }

        __syncthreads();
        float* Ps = Ks;
#pragma unroll
        for (int j = 0; j < 4; j++)
            *(float4*)&Ps[(tn + j) * FA_STRIDE + tm] =
                make_float4(s[0][j], s[1][j], s[2][j], s[3][j]);
        __syncthreads();

        // O += P V : pairs along d
#pragma unroll 8
        for (int kk = 0; kk < 64; kk++) {
            float4 pv = *(const float4*)&Ps[kk * FA_STRIDE + tm];
            const ull* vp = (const ull*)&Vs[kk * FA_STRIDE + tn];
            ull vb0 = vp[0], vb1 = vp[1];
            ull pp0 = pack2(pv.x, pv.x);
            ull pp1 = pack2(pv.y, pv.y);
            ull pp2 = pack2(pv.z, pv.z);
            ull pp3 = pack2(pv.w, pv.w);
            o2[0][0] = fma2(pp0, vb0, o2[0][0]); o2[0][1] = fma2(pp0, vb1, o2[0][1]);
            o2[1][0] = fma2(pp1, vb0, o2[1][0]); o2[1][1] = fma2(pp1, vb1, o2[1][1]);
            o2[2][0] = fma2(pp2, vb0, o2[2][0]); o2[2][1] = fma2(pp2, vb1, o2[2][1]);
            o2[3][0] = fma2(pp3, vb0, o2[3][0]); o2[3][1] = fma2(pp3, vb1, o2[3][1]);
        }
    }

#pragma unroll
    for (int i = 0; i < 4; i++) {
        float inv = 1.f / l_i[i];
        float2 a = unpack2(o2[i][0]);
        float2 bq = unpack2(o2[i][1]);
        float* op = &O[base + (size_t)(q0 + tm + i) * E_ + tn];
        *(float4*)op = make_float4(a.x * inv, a.y * inv, bq.x * inv, bq.y * inv);
    }
}

// ---------------------------------------------------------------------------
extern "C" void kernel_launch(void* const* d_in, const int* in_sizes, int n_in,
                              void* d_out, int out_size)
{
    const float* query = (const float*)d_in[0];
    const float* key   = (const float*)d_in[1];
    const float* value = (const float*)d_in[2];
    // d_in[3] = mask (causal, structural) — unused
    const float* w_q = (const float*)d_in[4];
    const float* w_k = (const float*)d_in[5];
    const float* w_v = (const float*)d_in[6];
    const float* w_o = (const float*)d_in[7];
    float* out = (float*)d_out;

    float *Qb, *Kb, *Vb, *Ab;
    cudaGetSymbolAddress((void**)&Qb, g_Q);
    cudaGetSymbolAddress((void**)&Kb, g_K);
    cudaGetSymbolAddress((void**)&Vb, g_V);
    cudaGetSymbolAddress((void**)&Ab, g_A);

    cudaFuncSetAttribute(flash_attn,
                         cudaFuncAttributeMaxDynamicSharedMemorySize, FA_SMEM);

    dim3 gg(E_ / 128, M_ / 128);   // (8, 32)
    sgemm_nt<<<gg, 256>>>(query, w_q, Qb, M_, E_, E_);
    sgemm_nt<<<gg, 256>>>(key,   w_k, Kb, M_, E_, E_);
    sgemm_nt<<<gg, 256>>>(value, w_v, Vb, M_, E_, E_);

    flash_attn<<<dim3(S_ / 64, H_, B_), 256, FA_SMEM>>>(Qb, Kb, Vb, Ab);

    sgemm_nt<<<gg, 256>>>(Ab, w_o, out, M_, E_, E_);
}

// round 5
// speedup vs baseline: 1.1006x; 1.0138x over previous
#include <cuda_runtime.h>
#include <cstdint>

#define B_ 2
#define S_ 2048
#define E_ 1024
#define H_ 16
#define D_ 64
#define M_ (B_*S_)   // 4096 rows

// Scratch (device globals; no allocation)
__device__ float g_Q[M_*E_];
__device__ float g_K[M_*E_];
__device__ float g_V[M_*E_];
__device__ float g_A[M_*E_];

// ---------------------------------------------------------------------------
// SGEMM "NT" (R1 version — measured at the 40 TF/s FFMA roofline)
// ---------------------------------------------------------------------------
__global__ __launch_bounds__(256)
void sgemm_nt(const float* __restrict__ A, const float* __restrict__ W,
              float* __restrict__ C, int M, int N, int K)
{
    __shared__ float As[16][132];
    __shared__ float Bs[16][132];

    const int tid = threadIdx.x;
    const int m0 = blockIdx.y * 128;
    const int n0 = blockIdx.x * 128;
    const int tx = tid & 15;
    const int ty = tid >> 4;
    const int tm = ty * 8;
    const int tn = tx * 8;

    const int lr = tid >> 2;
    const int lk = (tid & 3) * 4;

    float acc[8][8];
#pragma unroll
    for (int i = 0; i < 8; i++)
#pragma unroll
        for (int j = 0; j < 8; j++) acc[i][j] = 0.f;

    for (int k0 = 0; k0 < K; k0 += 16) {
#pragma unroll
        for (int rr = 0; rr < 2; rr++) {
            const int r = lr + rr * 64;
            float4 va = *(const float4*)&A[(size_t)(m0 + r) * K + k0 + lk];
            As[lk + 0][r] = va.x; As[lk + 1][r] = va.y;
            As[lk + 2][r] = va.z; As[lk + 3][r] = va.w;
            float4 vb = *(const float4*)&W[(size_t)(n0 + r) * K + k0 + lk];
            Bs[lk + 0][r] = vb.x; Bs[lk + 1][r] = vb.y;
            Bs[lk + 2][r] = vb.z; Bs[lk + 3][r] = vb.w;
        }
        __syncthreads();

#pragma unroll
        for (int kk = 0; kk < 16; kk++) {
            float a[8], b[8];
            float4 t;
            t = *(const float4*)&As[kk][tm];     a[0]=t.x; a[1]=t.y; a[2]=t.z; a[3]=t.w;
            t = *(const float4*)&As[kk][tm + 4]; a[4]=t.x; a[5]=t.y; a[6]=t.z; a[7]=t.w;
            t = *(const float4*)&Bs[kk][tn];     b[0]=t.x; b[1]=t.y; b[2]=t.z; b[3]=t.w;
            t = *(const float4*)&Bs[kk][tn + 4]; b[4]=t.x; b[5]=t.y; b[6]=t.z; b[7]=t.w;
#pragma unroll
            for (int i = 0; i < 8; i++)
#pragma unroll
                for (int j = 0; j < 8; j++)
                    acc[i][j] = fmaf(a[i], b[j], acc[i][j]);
        }
        __syncthreads();
    }

#pragma unroll
    for (int i = 0; i < 8; i++) {
        float* cp = &C[(size_t)(m0 + tm + i) * N + n0 + tn];
        *(float4*)&cp[0] = make_float4(acc[i][0], acc[i][1], acc[i][2], acc[i][3]);
        *(float4*)&cp[4] = make_float4(acc[i][4], acc[i][5], acc[i][6], acc[i][7]);
    }
}

// ---------------------------------------------------------------------------
// Fast 2^y for y <= 0 (clamped), FMA-pipe only. Max rel err ~8e-5.
// ---------------------------------------------------------------------------
__device__ __forceinline__ float fexp2(float y)
{
    y = fmaxf(y, -126.f);
    float n = floorf(y);
    float f = y - n;
    float p = fmaf(f, 0.0013333558f, 0.0096181291f);
    p = fmaf(f, p, 0.0555041087f);
    p = fmaf(f, p, 0.2402265069f);
    p = fmaf(f, p, 0.6931471806f);
    p = fmaf(f, p, 1.0f);
    return __int_as_float(__float_as_int(p) + (((int)n) << 23));
}

// log2(e) / sqrt(64)
#define EXP_C 0.18033688011112042f

// ---------------------------------------------------------------------------
// Flash attention v2 (fp32, causal). One CTA = (b, h, 128-row q tile).
// 256 threads as 16(tx) x 16(ty); micro-tile 8 q-rows x 4 k-cols.
// smem: Qs [d][q] 64x132, Ks [d][k] 64x68, Vs [k][d] 64x68, Ps [q][k] 128x68.
// Total 103424 B -> 2 CTAs/SM.
// ---------------------------------------------------------------------------
#define FA_QS  (64*132)
#define FA_KS  (64*68)
#define FA_VS  (64*68)
#define FA_PS  (128*68)
#define FA_SMEM ((FA_QS + FA_KS + FA_VS + FA_PS) * 4)

__global__ __launch_bounds__(256, 2)
void flash_attn(const float* __restrict__ Q, const float* __restrict__ K,
                const float* __restrict__ V, float* __restrict__ O)
{
    extern __shared__ float sm[];
    float* Qs = sm;                 // [d*132 + qrow]
    float* Ks = Qs + FA_QS;         // [d*68 + kk]
    float* Vs = Ks + FA_KS;         // [kk*68 + d]
    float* Ps = Vs + FA_VS;         // [qrow*68 + kk]

    const int tid = threadIdx.x;
    const int tx = tid & 15;
    const int ty = tid >> 4;
    const int tm = ty * 8;          // owned q-rows (local, 8)
    const int tn = tx * 4;          // owned cols (4)

    const int q0 = ((S_/128) - 1 - blockIdx.x) * 128;  // heavy tiles first
    const int h  = blockIdx.y;
    const int b  = blockIdx.z;
    const size_t base = (size_t)(b * S_) * E_ + h * 64;

    // Load Q tile transposed: Qs[d][row], 128 rows x 64 d
#pragma unroll
    for (int c = 0; c < 8; c++) {
        int f4 = tid + c * 256;          // 0..2047
        int r  = f4 >> 4;                // 0..127
        int d4 = (f4 & 15) * 4;
        float4 v = *(const float4*)&Q[base + (size_t)(q0 + r) * E_ + d4];
        Qs[(d4 + 0) * 132 + r] = v.x;
        Qs[(d4 + 1) * 132 + r] = v.y;
        Qs[(d4 + 2) * 132 + r] = v.z;
        Qs[(d4 + 3) * 132 + r] = v.w;
    }

    float o[8][4];
    float m_i[8], l_i[8];
#pragma unroll
    for (int i = 0; i < 8; i++) {
        m_i[i] = -1e30f; l_i[i] = 0.f;
#pragma unroll
        for (int j = 0; j < 4; j++) o[i][j] = 0.f;
    }

    for (int k0 = 0; k0 <= q0 + 64; k0 += 64) {
        __syncthreads();   // prev iteration's Ks/Vs/Ps reads done
        // Load K transposed Ks[d][kk]; V direct Vs[kk][d]  (64 rows)
#pragma unroll
        for (int c = 0; c < 4; c++) {
            int f4 = tid + c * 256;      // 0..1023
            int r  = f4 >> 4;            // 0..63
            int d4 = (f4 & 15) * 4;
            float4 kv = *(const float4*)&K[base + (size_t)(k0 + r) * E_ + d4];
            Ks[(d4 + 0) * 68 + r] = kv.x;
            Ks[(d4 + 1) * 68 + r] = kv.y;
            Ks[(d4 + 2) * 68 + r] = kv.z;
            Ks[(d4 + 3) * 68 + r] = kv.w;
            float4 vv = *(const float4*)&V[base + (size_t)(k0 + r) * E_ + d4];
            *(float4*)&Vs[r * 68 + d4] = vv;
        }
        __syncthreads();

        // S = Q K^T (raw, unscaled)
        float s[8][4];
#pragma unroll
        for (int i = 0; i < 8; i++)
#pragma unroll
            for (int j = 0; j < 4; j++) s[i][j] = 0.f;

#pragma unroll 8
        for (int d = 0; d < 64; d++) {
            float4 qa = *(const float4*)&Qs[d * 132 + tm];
            float4 qb = *(const float4*)&Qs[d * 132 + tm + 4];
            float4 kv = *(const float4*)&Ks[d * 68 + tn];
            float qv[8] = {qa.x, qa.y, qa.z, qa.w, qb.x, qb.y, qb.z, qb.w};
            float kb[4] = {kv.x, kv.y, kv.z, kv.w};
#pragma unroll
            for (int i = 0; i < 8; i++)
#pragma unroll
                for (int j = 0; j < 4; j++)
                    s[i][j] = fmaf(qv[i], kb[j], s[i][j]);
        }

        if (k0 >= q0) {   // diagonal / above-diagonal tiles: mask k > q
#pragma unroll
            for (int i = 0; i < 8; i++)
#pragma unroll
                for (int j = 0; j < 4; j++)
                    if (k0 + tn + j > q0 + tm + i) s[i][j] = -1e30f;
        }

        // Online softmax (scale folded into exp constant)
#pragma unroll
        for (int i = 0; i < 8; i++) {
            float rm = fmaxf(fmaxf(s[i][0], s[i][1]), fmaxf(s[i][2], s[i][3]));
#pragma unroll
            for (int off = 8; off >= 1; off >>= 1)
                rm = fmaxf(rm, __shfl_xor_sync(0xffffffffu, rm, off));
            float mnew = fmaxf(m_i[i], rm);
            float scal = fexp2((m_i[i] - mnew) * EXP_C);
            float sum = 0.f;
#pragma unroll
            for (int j = 0; j < 4; j++) {
                s[i][j] = fexp2((s[i][j] - mnew) * EXP_C);
                sum += s[i][j];
            }
#pragma unroll
            for (int off = 8; off >= 1; off >>= 1)
                sum += __shfl_xor_sync(0xffffffffu, sum, off);
            l_i[i] = l_i[i] * scal + sum;
            m_i[i] = mnew;
#pragma unroll
            for (int j = 0; j < 4; j++) o[i][j] *= scal;
        }

        // Write P row-major: Ps[q][k] (conflict-free float4 stores)
#pragma unroll
        for (int i = 0; i < 8; i++)
            *(float4*)&Ps[(tm + i) * 68 + tn] =
                make_float4(s[i][0], s[i][1], s[i][2], s[i][3]);
        __syncthreads();

        // O += P V : chunk kk by 4
#pragma unroll 4
        for (int k4 = 0; k4 < 64; k4 += 4) {
            float4 v0 = *(const float4*)&Vs[(k4 + 0) * 68 + tn];
            float4 v1 = *(const float4*)&Vs[(k4 + 1) * 68 + tn];
            float4 v2 = *(const float4*)&Vs[(k4 + 2) * 68 + tn];
            float4 v3 = *(const float4*)&Vs[(k4 + 3) * 68 + tn];
#pragma unroll
            for (int i = 0; i < 8; i++) {
                float4 pr = *(const float4*)&Ps[(tm + i) * 68 + k4];
                o[i][0] = fmaf(pr.x, v0.x, o[i][0]);
                o[i][1] = fmaf(pr.x, v0.y, o[i][1]);
                o[i][2] = fmaf(pr.x, v0.z, o[i][2]);
                o[i][3] = fmaf(pr.x, v0.w, o[i][3]);
                o[i][0] = fmaf(pr.y, v1.x, o[i][0]);
                o[i][1] = fmaf(pr.y, v1.y, o[i][1]);
                o[i][2] = fmaf(pr.y, v1.z, o[i][2]);
                o[i][3] = fmaf(pr.y, v1.w, o[i][3]);
                o[i][0] = fmaf(pr.z, v2.x, o[i][0]);
                o[i][1] = fmaf(pr.z, v2.y, o[i][1]);
                o[i][2] = fmaf(pr.z, v2.z, o[i][2]);
                o[i][3] = fmaf(pr.z, v2.w, o[i][3]);
                o[i][0] = fmaf(pr.w, v3.x, o[i][0]);
                o[i][1] = fmaf(pr.w, v3.y, o[i][1]);
                o[i][2] = fmaf(pr.w, v3.z, o[i][2]);
                o[i][3] = fmaf(pr.w, v3.w, o[i][3]);
            }
        }
    }

    // Normalize + store
#pragma unroll
    for (int i = 0; i < 8; i++) {
        float inv = 1.f / l_i[i];
        float* op = &O[base + (size_t)(q0 + tm + i) * E_ + tn];
        *(float4*)op = make_float4(o[i][0] * inv, o[i][1] * inv,
                                   o[i][2] * inv, o[i][3] * inv);
    }
}

// ---------------------------------------------------------------------------
extern "C" void kernel_launch(void* const* d_in, const int* in_sizes, int n_in,
                              void* d_out, int out_size)
{
    const float* query = (const float*)d_in[0];
    const float* key   = (const float*)d_in[1];
    const float* value = (const float*)d_in[2];
    // d_in[3] = mask (causal, structural) — unused
    const float* w_q = (const float*)d_in[4];
    const float* w_k = (const float*)d_in[5];
    const float* w_v = (const float*)d_in[6];
    const float* w_o = (const float*)d_in[7];
    float* out = (float*)d_out;

    float *Qb, *Kb, *Vb, *Ab;
    cudaGetSymbolAddress((void**)&Qb, g_Q);
    cudaGetSymbolAddress((void**)&Kb, g_K);
    cudaGetSymbolAddress((void**)&Vb, g_V);
    cudaGetSymbolAddress((void**)&Ab, g_A);

    cudaFuncSetAttribute(flash_attn,
                         cudaFuncAttributeMaxDynamicSharedMemorySize, FA_SMEM);

    dim3 gg(E_ / 128, M_ / 128);   // (8, 32)
    sgemm_nt<<<gg, 256>>>(query, w_q, Qb, M_, E_, E_);
    sgemm_nt<<<gg, 256>>>(key,   w_k, Kb, M_, E_, E_);
    sgemm_nt<<<gg, 256>>>(value, w_v, Vb, M_, E_, E_);

    flash_attn<<<dim3(S_ / 128, H_, B_), 256, FA_SMEM>>>(Qb, Kb, Vb, Ab);

    sgemm_nt<<<gg, 256>>>(Ab, w_o, out, M_, E_, E_);
}

// round 6
// speedup vs baseline: 1.2639x; 1.1483x over previous
#include <cuda_runtime.h>
#include <cuda_bf16.h>
#include <cstdint>

#define B_ 2
#define S_ 2048
#define E_ 1024
#define H_ 16
#define D_ 64
#define M_ (B_*S_)   // 4096 rows

// Scratch (device globals; no allocation)
__device__ float g_Q[M_*E_];
__device__ float g_K[M_*E_];
__device__ float g_V[M_*E_];
__device__ float g_A[M_*E_];
__device__ __align__(16) __nv_bfloat16 g_act_hi[M_*E_];
__device__ __align__(16) __nv_bfloat16 g_act_lo[M_*E_];
__device__ __align__(16) __nv_bfloat16 g_w_hi[E_*E_];
__device__ __align__(16) __nv_bfloat16 g_w_lo[E_*E_];

// ---------------- PTX helpers ----------------------------------------------
__device__ __forceinline__ uint32_t smem_u32(const void* p) {
    uint32_t a;
    asm("{ .reg .u64 t; cvta.to.shared.u64 t, %1; cvt.u32.u64 %0, t; }"
        : "=r"(a) : "l"(p));
    return a;
}
__device__ __forceinline__ void cp16(uint32_t dst, const void* src) {
    asm volatile("cp.async.cg.shared.global [%0], [%1], 16;" :: "r"(dst), "l"(src));
}
#define CP_COMMIT() asm volatile("cp.async.commit_group;" ::: "memory")
#define BAR(id, cnt) asm volatile("bar.sync %0, %1;" :: "r"(id), "r"(cnt) : "memory")

__device__ __forceinline__ void ldsm_x4(uint32_t& r0, uint32_t& r1,
                                        uint32_t& r2, uint32_t& r3, uint32_t addr) {
    asm volatile("ldmatrix.sync.aligned.m8n8.x4.shared.b16 {%0,%1,%2,%3}, [%4];"
                 : "=r"(r0), "=r"(r1), "=r"(r2), "=r"(r3) : "r"(addr));
}
__device__ __forceinline__ void mma_bf16(float* d, const uint32_t* a,
                                         uint32_t b0, uint32_t b1) {
    asm volatile(
        "mma.sync.aligned.m16n8k16.row.col.f32.bf16.bf16.f32 "
        "{%0,%1,%2,%3}, {%4,%5,%6,%7}, {%8,%9}, {%0,%1,%2,%3};"
        : "+f"(d[0]), "+f"(d[1]), "+f"(d[2]), "+f"(d[3])
        : "r"(a[0]), "r"(a[1]), "r"(a[2]), "r"(a[3]), "r"(b0), "r"(b1));
}
__device__ __forceinline__ uint32_t sw128(uint32_t off) {
    return off ^ ((off >> 3) & 0x70);
}

// ---------------------------------------------------------------------------
// Split fp32 -> (hi, lo) bf16 pair. n4 = n/4.
// ---------------------------------------------------------------------------
__global__ __launch_bounds__(256)
void split_bf16(const float* __restrict__ x, __nv_bfloat16* __restrict__ hi,
                __nv_bfloat16* __restrict__ lo, int n4)
{
    int i = blockIdx.x * blockDim.x + threadIdx.x;
    if (i >= n4) return;
    float4 v = ((const float4*)x)[i];
    __nv_bfloat16 h0 = __float2bfloat16(v.x);
    __nv_bfloat16 h1 = __float2bfloat16(v.y);
    __nv_bfloat16 h2 = __float2bfloat16(v.z);
    __nv_bfloat16 h3 = __float2bfloat16(v.w);
    __nv_bfloat16 l0 = __float2bfloat16(v.x - __bfloat162float(h0));
    __nv_bfloat16 l1 = __float2bfloat16(v.y - __bfloat162float(h1));
    __nv_bfloat16 l2 = __float2bfloat16(v.z - __bfloat162float(h2));
    __nv_bfloat16 l3 = __float2bfloat16(v.w - __bfloat162float(h3));
    __nv_bfloat162 ph0; ph0.x = h0; ph0.y = h1;
    __nv_bfloat162 ph1; ph1.x = h2; ph1.y = h3;
    __nv_bfloat162 pl0; pl0.x = l0; pl0.y = l1;
    __nv_bfloat162 pl1; pl1.x = l2; pl1.y = l3;
    ((__nv_bfloat162*)hi)[i*2]   = ph0;
    ((__nv_bfloat162*)hi)[i*2+1] = ph1;
    ((__nv_bfloat162*)lo)[i*2]   = pl0;
    ((__nv_bfloat162*)lo)[i*2+1] = pl1;
}

// ---------------------------------------------------------------------------
// HYBRID GEMM: C = A @ W^T (A:[4096,1024] fp32, W:[1024,1024] fp32, both NT)
//  - warps 0-7  (256 thr): exact fp32 FFMA over K [512, 1024)
//  - warps 8-15 (256 thr): bf16 HMMA, 3 slabs (hh, lh, hl) over K [0, 512)
// CTA tile 128x128. Tensor stages + staging in dynamic smem; FFMA tiles static.
// ---------------------------------------------------------------------------
#define KF0 512                      // fp32 path K start
#define T_NIT 24                     // 3 slabs * (512/64)
#define ATILE_B (128*128)            // 16KB: 128 rows x 64 bf16
#define STAGE_B (2*ATILE_B)          // 32KB per stage (A+B)
#define STAG_F  (128*132)            // fp32 staging floats
#define HY_DSMEM (STAG_F*4)          // 67584 B (>= 2*STAGE_B)

__device__ __forceinline__ void hy_load_tiles(
    const __nv_bfloat16* __restrict__ Ap, const __nv_bfloat16* __restrict__ Bp,
    int m0, int n0, int kc, uint32_t sa, uint32_t sbb, int t)
{
#pragma unroll
    for (int i = 0; i < 4; i++) {
        int cidx = t + i*256;            // 0..1023
        int row = cidx >> 3;             // 0..127
        int cb  = (cidx & 7) * 16;       // byte col within 128B row
        uint32_t sw = sw128((uint32_t)(row*128 + cb));
        cp16(sa  + sw, (const char*)(Ap + (size_t)(m0+row)*E_ + kc) + cb);
        cp16(sbb + sw, (const char*)(Bp + (size_t)(n0+row)*E_ + kc) + cb);
    }
}

__global__ __launch_bounds__(512)
void gemm_hybrid(const float* __restrict__ A, const float* __restrict__ W,
                 const __nv_bfloat16* __restrict__ Ahi, const __nv_bfloat16* __restrict__ Alo,
                 const __nv_bfloat16* __restrict__ Whi, const __nv_bfloat16* __restrict__ Wlo,
                 float* __restrict__ C)
{
    extern __shared__ char dsm[];
    __shared__ float As[16][132];
    __shared__ float Bs[16][132];
    float* stag = (float*)dsm;          // [128][132] fp32 staging (tensor partials)
    const uint32_t sb = smem_u32(dsm);  // tensor stage base

    const int tid = threadIdx.x;
    const int wid = tid >> 5;
    const int lane = tid & 31;
    const int m0 = blockIdx.y * 128;
    const int n0 = blockIdx.x * 128;

    if (wid < 8) {
        // ================= FFMA group: exact fp32 over K [512,1024) ========
        const int t  = tid;              // 0..255
        const int tx = t & 15;
        const int ty = t >> 4;
        const int tm = ty * 8;
        const int tn = tx * 8;
        const int lr = t >> 2;
        const int lk = (t & 3) * 4;

        float acc[8][8];
#pragma unroll
        for (int i = 0; i < 8; i++)
#pragma unroll
            for (int j = 0; j < 8; j++) acc[i][j] = 0.f;

        for (int k0 = KF0; k0 < E_; k0 += 16) {
#pragma unroll
            for (int rr = 0; rr < 2; rr++) {
                const int r = lr + rr * 64;
                float4 va = *(const float4*)&A[(size_t)(m0 + r) * E_ + k0 + lk];
                As[lk + 0][r] = va.x; As[lk + 1][r] = va.y;
                As[lk + 2][r] = va.z; As[lk + 3][r] = va.w;
                float4 vb = *(const float4*)&W[(size_t)(n0 + r) * E_ + k0 + lk];
                Bs[lk + 0][r] = vb.x; Bs[lk + 1][r] = vb.y;
                Bs[lk + 2][r] = vb.z; Bs[lk + 3][r] = vb.w;
            }
            BAR(1, 256);
#pragma unroll
            for (int kk = 0; kk < 16; kk++) {
                float a[8], b[8];
                float4 tt;
                tt = *(const float4*)&As[kk][tm];     a[0]=tt.x; a[1]=tt.y; a[2]=tt.z; a[3]=tt.w;
                tt = *(const float4*)&As[kk][tm + 4]; a[4]=tt.x; a[5]=tt.y; a[6]=tt.z; a[7]=tt.w;
                tt = *(const float4*)&Bs[kk][tn];     b[0]=tt.x; b[1]=tt.y; b[2]=tt.z; b[3]=tt.w;
                tt = *(const float4*)&Bs[kk][tn + 4]; b[4]=tt.x; b[5]=tt.y; b[6]=tt.z; b[7]=tt.w;
#pragma unroll
                for (int i = 0; i < 8; i++)
#pragma unroll
                    for (int j = 0; j < 8; j++)
                        acc[i][j] = fmaf(a[i], b[j], acc[i][j]);
            }
            BAR(1, 256);
        }

        BAR(0, 512);   // tensor partials staged

#pragma unroll
        for (int i = 0; i < 8; i++) {
            const float* sp = &stag[(tm + i) * 132 + tn];
            float4 s0 = *(const float4*)&sp[0];
            float4 s1 = *(const float4*)&sp[4];
            float* cp = &C[(size_t)(m0 + tm + i) * E_ + n0 + tn];
            *(float4*)&cp[0] = make_float4(acc[i][0] + s0.x, acc[i][1] + s0.y,
                                           acc[i][2] + s0.z, acc[i][3] + s0.w);
            *(float4*)&cp[4] = make_float4(acc[i][4] + s1.x, acc[i][5] + s1.y,
                                           acc[i][6] + s1.z, acc[i][7] + s1.w);
        }
    } else {
        // ================= Tensor group: 3-slab bf16 HMMA over K [0,512) ===
        const int t = tid - 256;         // 0..255
        const int wt = wid - 8;          // 0..7
        const int wm = (wt & 1) * 64;
        const int wn = (wt >> 1) * 32;

        float acc[4][4][4];
#pragma unroll
        for (int mi = 0; mi < 4; mi++)
#pragma unroll
            for (int ni = 0; ni < 4; ni++)
#pragma unroll
                for (int q = 0; q < 4; q++) acc[mi][ni][q] = 0.f;

        const int lrow = lane & 15;
        const int lcb  = (lane >> 4) * 16;

        hy_load_tiles(Ahi, Whi, m0, n0, 0, sb, sb + ATILE_B, t);
        CP_COMMIT();

        for (int iter = 0; iter < T_NIT; iter++) {
            const int s = iter & 1;
            if (iter + 1 < T_NIT) {
                const int nit  = iter + 1;
                const int slab = nit >> 3;
                const int kc   = (nit & 7) * 64;
                const __nv_bfloat16* Ap = (slab == 1) ? Alo : Ahi;
                const __nv_bfloat16* Bp = (slab == 2) ? Wlo : Whi;
                hy_load_tiles(Ap, Bp, m0, n0, kc,
                              sb + (s^1)*STAGE_B, sb + (s^1)*STAGE_B + ATILE_B, t);
                CP_COMMIT();
                asm volatile("cp.async.wait_group 1;" ::: "memory");
            } else {
                asm volatile("cp.async.wait_group 0;" ::: "memory");
            }
            BAR(2, 256);

            const uint32_t sa  = sb + s*STAGE_B;
            const uint32_t sbb = sa + ATILE_B;
#pragma unroll
            for (int kk = 0; kk < 4; kk++) {
                uint32_t a[4][4], bfr[2][4];
#pragma unroll
                for (int mi = 0; mi < 4; mi++) {
                    uint32_t off = (uint32_t)((wm + mi*16 + lrow)*128 + kk*32 + lcb);
                    ldsm_x4(a[mi][0], a[mi][1], a[mi][2], a[mi][3], sa + sw128(off));
                }
#pragma unroll
                for (int hh = 0; hh < 2; hh++) {
                    uint32_t off = (uint32_t)((wn + hh*16 + lrow)*128 + kk*32 + lcb);
                    ldsm_x4(bfr[hh][0], bfr[hh][1], bfr[hh][2], bfr[hh][3], sbb + sw128(off));
                }
#pragma unroll
                for (int mi = 0; mi < 4; mi++) {
                    mma_bf16(acc[mi][0], a[mi], bfr[0][0], bfr[0][2]);
                    mma_bf16(acc[mi][1], a[mi], bfr[0][1], bfr[0][3]);
                    mma_bf16(acc[mi][2], a[mi], bfr[1][0], bfr[1][2]);
                    mma_bf16(acc[mi][3], a[mi], bfr[1][1], bfr[1][3]);
                }
            }
            BAR(2, 256);
        }

        // stage fp32 partials: frag (r=lane>>2, c=2*(lane&3))
        const int r  = lane >> 2;
        const int c2 = (lane & 3) * 2;
#pragma unroll
        for (int mi = 0; mi < 4; mi++)
#pragma unroll
            for (int ni = 0; ni < 4; ni++) {
                const int row = wm + mi*16 + r;
                const int col = wn + ni*8 + c2;
                *(float2*)&stag[row * 132 + col]       = make_float2(acc[mi][ni][0], acc[mi][ni][1]);
                *(float2*)&stag[(row + 8) * 132 + col] = make_float2(acc[mi][ni][2], acc[mi][ni][3]);
            }

        BAR(0, 512);   // hand off to FFMA group
    }
}

// ---------------------------------------------------------------------------
// Fast 2^y (y <= 0), FMA-pipe only. Max rel err ~8e-5.
// ---------------------------------------------------------------------------
__device__ __forceinline__ float fexp2(float y)
{
    y = fmaxf(y, -126.f);
    float n = floorf(y);
    float f = y - n;
    float p = fmaf(f, 0.0013333558f, 0.0096181291f);
    p = fmaf(f, p, 0.0555041087f);
    p = fmaf(f, p, 0.2402265069f);
    p = fmaf(f, p, 0.6931471806f);
    p = fmaf(f, p, 1.0f);
    return __int_as_float(__float_as_int(p) + (((int)n) << 23));
}
#define EXP_C 0.18033688011112042f   // log2(e)/sqrt(64)

// ---------------------------------------------------------------------------
// Flash attention (fp32, causal) — R5 version.
// ---------------------------------------------------------------------------
#define FA_QS  (64*132)
#define FA_KS  (64*68)
#define FA_VS  (64*68)
#define FA_PS  (128*68)
#define FA_SMEM ((FA_QS + FA_KS + FA_VS + FA_PS) * 4)

__global__ __launch_bounds__(256, 2)
void flash_attn(const float* __restrict__ Q, const float* __restrict__ K,
                const float* __restrict__ V, float* __restrict__ O)
{
    extern __shared__ float sm[];
    float* Qs = sm;
    float* Ks = Qs + FA_QS;
    float* Vs = Ks + FA_KS;
    float* Ps = Vs + FA_VS;

    const int tid = threadIdx.x;
    const int tx = tid & 15;
    const int ty = tid >> 4;
    const int tm = ty * 8;
    const int tn = tx * 4;

    const int q0 = ((S_/128) - 1 - blockIdx.x) * 128;
    const int h  = blockIdx.y;
    const int b  = blockIdx.z;
    const size_t base = (size_t)(b * S_) * E_ + h * 64;

#pragma unroll
    for (int c = 0; c < 8; c++) {
        int f4 = tid + c * 256;
        int r  = f4 >> 4;
        int d4 = (f4 & 15) * 4;
        float4 v = *(const float4*)&Q[base + (size_t)(q0 + r) * E_ + d4];
        Qs[(d4 + 0) * 132 + r] = v.x;
        Qs[(d4 + 1) * 132 + r] = v.y;
        Qs[(d4 + 2) * 132 + r] = v.z;
        Qs[(d4 + 3) * 132 + r] = v.w;
    }

    float o[8][4];
    float m_i[8], l_i[8];
#pragma unroll
    for (int i = 0; i < 8; i++) {
        m_i[i] = -1e30f; l_i[i] = 0.f;
#pragma unroll
        for (int j = 0; j < 4; j++) o[i][j] = 0.f;
    }

    for (int k0 = 0; k0 <= q0 + 64; k0 += 64) {
        __syncthreads();
#pragma unroll
        for (int c = 0; c < 4; c++) {
            int f4 = tid + c * 256;
            int r  = f4 >> 4;
            int d4 = (f4 & 15) * 4;
            float4 kv = *(const float4*)&K[base + (size_t)(k0 + r) * E_ + d4];
            Ks[(d4 + 0) * 68 + r] = kv.x;
            Ks[(d4 + 1) * 68 + r] = kv.y;
            Ks[(d4 + 2) * 68 + r] = kv.z;
            Ks[(d4 + 3) * 68 + r] = kv.w;
            float4 vv = *(const float4*)&V[base + (size_t)(k0 + r) * E_ + d4];
            *(float4*)&Vs[r * 68 + d4] = vv;
        }
        __syncthreads();

        float s[8][4];
#pragma unroll
        for (int i = 0; i < 8; i++)
#pragma unroll
            for (int j = 0; j < 4; j++) s[i][j] = 0.f;

#pragma unroll 8
        for (int d = 0; d < 64; d++) {
            float4 qa = *(const float4*)&Qs[d * 132 + tm];
            float4 qb = *(const float4*)&Qs[d * 132 + tm + 4];
            float4 kv = *(const float4*)&Ks[d * 68 + tn];
            float qv[8] = {qa.x, qa.y, qa.z, qa.w, qb.x, qb.y, qb.z, qb.w};
            float kb[4] = {kv.x, kv.y, kv.z, kv.w};
#pragma unroll
            for (int i = 0; i < 8; i++)
#pragma unroll
                for (int j = 0; j < 4; j++)
                    s[i][j] = fmaf(qv[i], kb[j], s[i][j]);
        }

        if (k0 >= q0) {
#pragma unroll
            for (int i = 0; i < 8; i++)
#pragma unroll
                for (int j = 0; j < 4; j++)
                    if (k0 + tn + j > q0 + tm + i) s[i][j] = -1e30f;
        }

#pragma unroll
        for (int i = 0; i < 8; i++) {
            float rm = fmaxf(fmaxf(s[i][0], s[i][1]), fmaxf(s[i][2], s[i][3]));
#pragma unroll
            for (int off = 8; off >= 1; off >>= 1)
                rm = fmaxf(rm, __shfl_xor_sync(0xffffffffu, rm, off));
            float mnew = fmaxf(m_i[i], rm);
            float scal = fexp2((m_i[i] - mnew) * EXP_C);
            float sum = 0.f;
#pragma unroll
            for (int j = 0; j < 4; j++) {
                s[i][j] = fexp2((s[i][j] - mnew) * EXP_C);
                sum += s[i][j];
            }
#pragma unroll
            for (int off = 8; off >= 1; off >>= 1)
                sum += __shfl_xor_sync(0xffffffffu, sum, off);
            l_i[i] = l_i[i] * scal + sum;
            m_i[i] = mnew;
#pragma unroll
            for (int j = 0; j < 4; j++) o[i][j] *= scal;
        }

#pragma unroll
        for (int i = 0; i < 8; i++)
            *(float4*)&Ps[(tm + i) * 68 + tn] =
                make_float4(s[i][0], s[i][1], s[i][2], s[i][3]);
        __syncthreads();

#pragma unroll 4
        for (int k4 = 0; k4 < 64; k4 += 4) {
            float4 v0 = *(const float4*)&Vs[(k4 + 0) * 68 + tn];
            float4 v1 = *(const float4*)&Vs[(k4 + 1) * 68 + tn];
            float4 v2 = *(const float4*)&Vs[(k4 + 2) * 68 + tn];
            float4 v3 = *(const float4*)&Vs[(k4 + 3) * 68 + tn];
#pragma unroll
            for (int i = 0; i < 8; i++) {
                float4 pr = *(const float4*)&Ps[(tm + i) * 68 + k4];
                o[i][0] = fmaf(pr.x, v0.x, o[i][0]);
                o[i][1] = fmaf(pr.x, v0.y, o[i][1]);
                o[i][2] = fmaf(pr.x, v0.z, o[i][2]);
                o[i][3] = fmaf(pr.x, v0.w, o[i][3]);
                o[i][0] = fmaf(pr.y, v1.x, o[i][0]);
                o[i][1] = fmaf(pr.y, v1.y, o[i][1]);
                o[i][2] = fmaf(pr.y, v1.z, o[i][2]);
                o[i][3] = fmaf(pr.y, v1.w, o[i][3]);
                o[i][0] = fmaf(pr.z, v2.x, o[i][0]);
                o[i][1] = fmaf(pr.z, v2.y, o[i][1]);
                o[i][2] = fmaf(pr.z, v2.z, o[i][2]);
                o[i][3] = fmaf(pr.z, v2.w, o[i][3]);
                o[i][0] = fmaf(pr.w, v3.x, o[i][0]);
                o[i][1] = fmaf(pr.w, v3.y, o[i][1]);
                o[i][2] = fmaf(pr.w, v3.z, o[i][2]);
                o[i][3] = fmaf(pr.w, v3.w, o[i][3]);
            }
        }
    }

#pragma unroll
    for (int i = 0; i < 8; i++) {
        float inv = 1.f / l_i[i];
        float* op = &O[base + (size_t)(q0 + tm + i) * E_ + tn];
        *(float4*)op = make_float4(o[i][0] * inv, o[i][1] * inv,
                                   o[i][2] * inv, o[i][3] * inv);
    }
}

// ---------------------------------------------------------------------------
extern "C" void kernel_launch(void* const* d_in, const int* in_sizes, int n_in,
                              void* d_out, int out_size)
{
    const float* query = (const float*)d_in[0];
    const float* key   = (const float*)d_in[1];
    const float* value = (const float*)d_in[2];
    // d_in[3] = mask (causal, structural) — unused
    const float* w_q = (const float*)d_in[4];
    const float* w_k = (const float*)d_in[5];
    const float* w_v = (const float*)d_in[6];
    const float* w_o = (const float*)d_in[7];
    float* out = (float*)d_out;

    float *Qb, *Kb, *Vb, *Ab;
    cudaGetSymbolAddress((void**)&Qb, g_Q);
    cudaGetSymbolAddress((void**)&Kb, g_K);
    cudaGetSymbolAddress((void**)&Vb, g_V);
    cudaGetSymbolAddress((void**)&Ab, g_A);
    __nv_bfloat16 *ah, *al, *wh, *wl;
    cudaGetSymbolAddress((void**)&ah, g_act_hi);
    cudaGetSymbolAddress((void**)&al, g_act_lo);
    cudaGetSymbolAddress((void**)&wh, g_w_hi);
    cudaGetSymbolAddress((void**)&wl, g_w_lo);

    cudaFuncSetAttribute(flash_attn,
                         cudaFuncAttributeMaxDynamicSharedMemorySize, FA_SMEM);
    cudaFuncSetAttribute(gemm_hybrid,
                         cudaFuncAttributeMaxDynamicSharedMemorySize, HY_DSMEM);

    const int actN4 = M_ * E_ / 4;
    const int wN4   = E_ * E_ / 4;
    dim3 gg(E_ / 128, M_ / 128);   // (8, 32)

    split_bf16<<<actN4/256, 256>>>(query, ah, al, actN4);
    split_bf16<<<wN4/256,  256>>>(w_q,  wh, wl, wN4);
    gemm_hybrid<<<gg, 512, HY_DSMEM>>>(query, w_q, ah, al, wh, wl, Qb);

    split_bf16<<<actN4/256, 256>>>(key, ah, al, actN4);
    split_bf16<<<wN4/256,  256>>>(w_k, wh, wl, wN4);
    gemm_hybrid<<<gg, 512, HY_DSMEM>>>(key, w_k, ah, al, wh, wl, Kb);

    split_bf16<<<actN4/256, 256>>>(value, ah, al, actN4);
    split_bf16<<<wN4/256,  256>>>(w_v, wh, wl, wN4);
    gemm_hybrid<<<gg, 512, HY_DSMEM>>>(value, w_v, ah, al, wh, wl, Vb);

    flash_attn<<<dim3(S_ / 128, H_, B_), 256, FA_SMEM>>>(Qb, Kb, Vb, Ab);

    split_bf16<<<actN4/256, 256>>>(Ab, ah, al, actN4);
    split_bf16<<<wN4/256,  256>>>(w_o, wh, wl, wN4);
    gemm_hybrid<<<gg, 512, HY_DSMEM>>>(Ab, w_o, ah, al, wh, wl, out);
}